// round 14
// baseline (speedup 1.0000x reference)
#include <cuda_runtime.h>
#include <cuda_bf16.h>
#include <math.h>
#include <stdint.h>

// Problem constants
#define BSZ 4
#define SEQ 1024
#define DMODEL 512
#define NHEAD 8
#define DHEAD 64
#define NLAYER 4
#define ROWS (BSZ * SEQ)          // 4096
#define MAT (DMODEL * DMODEL)     // 262144

// ---------------- scratch (device globals; no allocation) ----------------
__device__ float g_r[ROWS * DMODEL];
__device__ __nv_bfloat16 g_wh[24 * MAT];
__device__ __nv_bfloat16 g_wl[24 * MAT];
__device__ __nv_bfloat16 g_ah[ROWS * DMODEL];
__device__ __nv_bfloat16 g_al[ROWS * DMODEL];
__device__ __nv_bfloat16 g_qh[ROWS * DMODEL];
__device__ __nv_bfloat16 g_ql[ROWS * DMODEL];
__device__ __nv_bfloat16 g_kh[ROWS * DMODEL];
__device__ __nv_bfloat16 g_kl[ROWS * DMODEL];
__device__ __nv_bfloat16 g_vh[ROWS * DMODEL];
__device__ __nv_bfloat16 g_vl[ROWS * DMODEL];

// ---------------- PTX helpers (sm_80+ features only) ----------------
__device__ __forceinline__ uint32_t smem_to_u32(const void* p) {
    uint32_t a;
    asm("{ .reg .u64 t; cvta.to.shared.u64 t, %1; cvt.u32.u64 %0, t; }" : "=r"(a) : "l"(p));
    return a;
}
__device__ __forceinline__ void cp_async16(uint32_t dst, const void* src) {
    asm volatile("cp.async.cg.shared.global [%0], [%1], 16;" :: "r"(dst), "l"(src));
}
__device__ __forceinline__ void ldsm4(uint32_t& r0, uint32_t& r1, uint32_t& r2, uint32_t& r3,
                                      uint32_t a) {
    asm volatile("ldmatrix.sync.aligned.m8n8.x4.shared.b16 {%0,%1,%2,%3}, [%4];"
                 : "=r"(r0), "=r"(r1), "=r"(r2), "=r"(r3) : "r"(a));
}
__device__ __forceinline__ void ldsm4t(uint32_t& r0, uint32_t& r1, uint32_t& r2, uint32_t& r3,
                                       uint32_t a) {
    asm volatile("ldmatrix.sync.aligned.m8n8.x4.trans.shared.b16 {%0,%1,%2,%3}, [%4];"
                 : "=r"(r0), "=r"(r1), "=r"(r2), "=r"(r3) : "r"(a));
}
__device__ __forceinline__ void mma16816(float* c, uint32_t a0, uint32_t a1, uint32_t a2,
                                         uint32_t a3, uint32_t b0, uint32_t b1) {
    asm volatile(
        "mma.sync.aligned.m16n8k16.row.col.f32.bf16.bf16.f32 "
        "{%0,%1,%2,%3}, {%4,%5,%6,%7}, {%8,%9}, {%0,%1,%2,%3};"
        : "+f"(c[0]), "+f"(c[1]), "+f"(c[2]), "+f"(c[3])
        : "r"(a0), "r"(a1), "r"(a2), "r"(a3), "r"(b0), "r"(b1));
}

__device__ __forceinline__ void split_store(float v, __nv_bfloat16* hi, __nv_bfloat16* lo) {
    __nv_bfloat16 h = __float2bfloat16(v);
    *hi = h;
    *lo = __float2bfloat16(v - __bfloat162float(h));
}

// ---------------- LayerNorm helpers ----------------
__inline__ __device__ float warp_sum(float v) {
#pragma unroll
    for (int o = 16; o; o >>= 1) v += __shfl_xor_sync(0xffffffffu, v, o);
    return v;
}

__device__ __forceinline__ float4 ln_row(const float* __restrict__ x,
                                         const float* __restrict__ w,
                                         const float* __restrict__ b,
                                         int row, int t) {
    const float4 v = *(const float4*)&x[(size_t)row * DMODEL + t * 4];
    float s  = v.x + v.y + v.z + v.w;
    float sq = v.x * v.x + v.y * v.y + v.z * v.z + v.w * v.w;
    __shared__ float red[8];
    float s1 = warp_sum(s), s2 = warp_sum(sq);
    int warp = t >> 5, lane = t & 31;
    if (lane == 0) { red[warp] = s1; red[4 + warp] = s2; }
    __syncthreads();
    s1 = red[0] + red[1] + red[2] + red[3];
    s2 = red[4] + red[5] + red[6] + red[7];
    float mu = s1 * (1.0f / DMODEL);
    float var = s2 * (1.0f / DMODEL) - mu * mu;
    float inv = rsqrtf(var + 1e-5f);
    const float4 wv = *(const float4*)&w[t * 4];
    const float4 bv = *(const float4*)&b[t * 4];
    float4 o;
    o.x = (v.x - mu) * inv * wv.x + bv.x;
    o.y = (v.y - mu) * inv * wv.y + bv.y;
    o.z = (v.z - mu) * inv * wv.z + bv.z;
    o.w = (v.w - mu) * inv * wv.w + bv.w;
    return o;
}

__global__ void ln_kernel(const float* __restrict__ x,
                          const float* __restrict__ w,
                          const float* __restrict__ b,
                          float* __restrict__ y) {
    int row = blockIdx.x, t = threadIdx.x;
    float4 o = ln_row(x, w, b, row, t);
    *(float4*)&y[(size_t)row * DMODEL + t * 4] = o;
}

__global__ void ln_split_kernel(const float* __restrict__ x,
                                const float* __restrict__ w,
                                const float* __restrict__ b,
                                __nv_bfloat16* __restrict__ hi,
                                __nv_bfloat16* __restrict__ lo) {
    int row = blockIdx.x, t = threadIdx.x;
    float4 o = ln_row(x, w, b, row, t);
    __nv_bfloat16 hv[4], lv[4];
    split_store(o.x, &hv[0], &lv[0]);
    split_store(o.y, &hv[1], &lv[1]);
    split_store(o.z, &hv[2], &lv[2]);
    split_store(o.w, &hv[3], &lv[3]);
    int i = row * (DMODEL / 4) + t;
    ((uint64_t*)hi)[i] = *(uint64_t*)hv;
    ((uint64_t*)lo)[i] = *(uint64_t*)lv;
}

// LN3 then LN1(next layer) fused
__global__ void ln3_ln1_kernel(const float* __restrict__ x,
                               const float* __restrict__ w3, const float* __restrict__ b3,
                               const float* __restrict__ w1, const float* __restrict__ b1,
                               float* __restrict__ y,
                               __nv_bfloat16* __restrict__ hi,
                               __nv_bfloat16* __restrict__ lo) {
    int row = blockIdx.x, t = threadIdx.x;
    int warp = t >> 5, lane = t & 31;
    __shared__ float red[8];
    const float4 v = *(const float4*)&x[(size_t)row * DMODEL + t * 4];
    float s = v.x + v.y + v.z + v.w;
    float sq = v.x * v.x + v.y * v.y + v.z * v.z + v.w * v.w;
    float s1 = warp_sum(s), s2 = warp_sum(sq);
    if (lane == 0) { red[warp] = s1; red[4 + warp] = s2; }
    __syncthreads();
    s1 = red[0] + red[1] + red[2] + red[3];
    s2 = red[4] + red[5] + red[6] + red[7];
    float mu = s1 * (1.0f / DMODEL);
    float var = s2 * (1.0f / DMODEL) - mu * mu;
    float inv = rsqrtf(var + 1e-5f);
    const float4 w3v = *(const float4*)&w3[t * 4];
    const float4 b3v = *(const float4*)&b3[t * 4];
    float4 o3;
    o3.x = (v.x - mu) * inv * w3v.x + b3v.x;
    o3.y = (v.y - mu) * inv * w3v.y + b3v.y;
    o3.z = (v.z - mu) * inv * w3v.z + b3v.z;
    o3.w = (v.w - mu) * inv * w3v.w + b3v.w;
    *(float4*)&y[(size_t)row * DMODEL + t * 4] = o3;
    __syncthreads();
    s = o3.x + o3.y + o3.z + o3.w;
    sq = o3.x * o3.x + o3.y * o3.y + o3.z * o3.z + o3.w * o3.w;
    s1 = warp_sum(s); s2 = warp_sum(sq);
    if (lane == 0) { red[warp] = s1; red[4 + warp] = s2; }
    __syncthreads();
    s1 = red[0] + red[1] + red[2] + red[3];
    s2 = red[4] + red[5] + red[6] + red[7];
    mu = s1 * (1.0f / DMODEL);
    var = s2 * (1.0f / DMODEL) - mu * mu;
    inv = rsqrtf(var + 1e-5f);
    const float4 w1v = *(const float4*)&w1[t * 4];
    const float4 b1v = *(const float4*)&b1[t * 4];
    float o1[4];
    o1[0] = (o3.x - mu) * inv * w1v.x + b1v.x;
    o1[1] = (o3.y - mu) * inv * w1v.y + b1v.y;
    o1[2] = (o3.z - mu) * inv * w1v.z + b1v.z;
    o1[3] = (o3.w - mu) * inv * w1v.w + b1v.w;
    __nv_bfloat16 hv[4], lv[4];
#pragma unroll
    for (int q = 0; q < 4; q++) split_store(o1[q], &hv[q], &lv[q]);
    int i = row * (DMODEL / 4) + t;
    ((uint64_t*)hi)[i] = *(uint64_t*)hv;
    ((uint64_t*)lo)[i] = *(uint64_t*)lv;
}

// ---------------- weight prep ----------------
__global__ void weight_prep(const float* __restrict__ Wq, const float* __restrict__ Wk,
                            const float* __restrict__ Wv, const float* __restrict__ Wr,
                            const float* __restrict__ Wo, const float* __restrict__ Oc,
                            __nv_bfloat16* __restrict__ wh, __nv_bfloat16* __restrict__ wl) {
    int i = blockIdx.x * blockDim.x + threadIdx.x;
    const int per = MAT / 4;
    if (i >= 24 * per) return;
    int s = i / per;
    int off = i - s * per;
    const float* src;
    if (s < 16) {
        int l = s >> 2, t = s & 3;
        src = (t == 0 ? Wq : t == 1 ? Wk : t == 2 ? Wv : Wr) + (size_t)l * MAT;
    } else if (s < 20) {
        src = Wo + (size_t)(s - 16) * MAT;
    } else {
        src = Oc + (size_t)(s - 20) * MAT;
    }
    float4 v = ((const float4*)src)[off];
    __nv_bfloat16 hv[4], lv[4];
    split_store(v.x, &hv[0], &lv[0]);
    split_store(v.y, &hv[1], &lv[1]);
    split_store(v.z, &hv[2], &lv[2]);
    split_store(v.w, &hv[3], &lv[3]);
    ((uint64_t*)wh)[i] = *(uint64_t*)hv;
    ((uint64_t*)wl)[i] = *(uint64_t*)lv;
}

// ---------------- shared GEMM mainloop (tile-once 3-split, 3-stage ring) -----
// 8 K-chunks of 64. Per stage (64KB): Ah@0 Al@16384 Wh@32768 Wl@49152.
// 3-stage ring -> 192KB smem; wait_group 2 keeps staging latency fully hidden.
#define GEMM_SMEM 196608
#define NCHUNK 8

__device__ __forceinline__ void gemm_stage(uint32_t smb, int tid, int m0, int n0, int kc, int s,
                                           const __nv_bfloat16* ah, const __nv_bfloat16* al,
                                           const __nv_bfloat16* wh, const __nv_bfloat16* wl) {
    int row = tid >> 1;
    int g0 = (tid & 1) * 4;
    const char* pa0 = (const char*)(ah + (size_t)(m0 + row) * DMODEL + kc);
    const char* pa1 = (const char*)(al + (size_t)(m0 + row) * DMODEL + kc);
    const char* pb0 = (const char*)(wh + (size_t)(n0 + row) * DMODEL + kc);
    const char* pb1 = (const char*)(wl + (size_t)(n0 + row) * DMODEL + kc);
    uint32_t base = smb + s * 65536 + row * 128;
#pragma unroll
    for (int j = 0; j < 4; j++) {
        int g = g0 + j;
        uint32_t so = (uint32_t)((g ^ (row & 7)) << 4);
        cp_async16(base + so, pa0 + g * 16);
        cp_async16(base + 16384 + so, pa1 + g * 16);
        cp_async16(base + 32768 + so, pb0 + g * 16);
        cp_async16(base + 49152 + so, pb1 + g * 16);
    }
}

__device__ __forceinline__ void gemm_compute(uint32_t smb, int s, int wm, int wn, int lane,
                                             float acc[4][4][4]) {
    uint32_t A0 = smb + s * 65536;
    uint32_t A1 = A0 + 16384;
    uint32_t B0 = A0 + 32768;
    uint32_t B1 = A0 + 49152;
#pragma unroll
    for (int k16 = 0; k16 < 4; k16++) {
        uint32_t aH[4][4], aL[4][4];
#pragma unroll
        for (int mi = 0; mi < 4; mi++) {
            int row = wm + mi * 16 + (lane & 15);
            int g = k16 * 2 + (lane >> 4);
            uint32_t so = (uint32_t)(row * 128 + ((g ^ (row & 7)) << 4));
            ldsm4(aH[mi][0], aH[mi][1], aH[mi][2], aH[mi][3], A0 + so);
            ldsm4(aL[mi][0], aL[mi][1], aL[mi][2], aL[mi][3], A1 + so);
        }
        uint32_t bH[2][4], bL[2][4];
#pragma unroll
        for (int nj = 0; nj < 2; nj++) {
            int row = wn + nj * 16 + ((lane >> 4) << 3) + (lane & 7);
            int g = k16 * 2 + ((lane >> 3) & 1);
            uint32_t so = (uint32_t)(row * 128 + ((g ^ (row & 7)) << 4));
            ldsm4(bH[nj][0], bH[nj][1], bH[nj][2], bH[nj][3], B0 + so);
            ldsm4(bL[nj][0], bL[nj][1], bL[nj][2], bL[nj][3], B1 + so);
        }
#pragma unroll
        for (int mi = 0; mi < 4; mi++)
#pragma unroll
            for (int ni = 0; ni < 4; ni++) {
                uint32_t h0 = bH[ni >> 1][(ni & 1) * 2], h1 = bH[ni >> 1][(ni & 1) * 2 + 1];
                uint32_t l0 = bL[ni >> 1][(ni & 1) * 2], l1 = bL[ni >> 1][(ni & 1) * 2 + 1];
                mma16816(acc[mi][ni], aH[mi][0], aH[mi][1], aH[mi][2], aH[mi][3], h0, h1);
                mma16816(acc[mi][ni], aH[mi][0], aH[mi][1], aH[mi][2], aH[mi][3], l0, l1);
                mma16816(acc[mi][ni], aL[mi][0], aL[mi][1], aL[mi][2], aL[mi][3], h0, h1);
            }
    }
}

#define GEMM_MAINLOOP(AH, AL, WHp, WLp, M0, N0)                                       \
    gemm_stage(smb, tid, M0, N0, 0, 0, AH, AL, WHp, WLp);                             \
    asm volatile("cp.async.commit_group;");                                           \
    gemm_stage(smb, tid, M0, N0, 64, 1, AH, AL, WHp, WLp);                            \
    asm volatile("cp.async.commit_group;");                                           \
    for (int c = 0; c < NCHUNK; c++) {                                                \
        if (c + 2 < NCHUNK) {                                                         \
            gemm_stage(smb, tid, M0, N0, (c + 2) * 64, (c + 2) % 3, AH, AL, WHp, WLp);\
            asm volatile("cp.async.commit_group;");                                   \
        }                                                                             \
        if (c + 2 < NCHUNK)      asm volatile("cp.async.wait_group 2;");              \
        else if (c + 1 < NCHUNK) asm volatile("cp.async.wait_group 1;");              \
        else                     asm volatile("cp.async.wait_group 0;");              \
        __syncthreads();                                                              \
        gemm_compute(smb, c % 3, wm, wn, lane, acc);                                  \
        __syncthreads();                                                              \
    }

// ---------------- standard GEMM (fp32 out, +bias +res) ----------------
template <bool BIAS, bool RES>
__global__ __launch_bounds__(256, 1)
void mma_gemm(const __nv_bfloat16* __restrict__ ah, const __nv_bfloat16* __restrict__ al,
              const __nv_bfloat16* __restrict__ wh, const __nv_bfloat16* __restrict__ wl,
              const float* __restrict__ bias, const float* __restrict__ res,
              float* __restrict__ C) {
    extern __shared__ char smem[];
    const uint32_t smb = smem_to_u32(smem);
    const int tid = threadIdx.x;
    const int wid = tid >> 5, lane = tid & 31;
    const int n0 = blockIdx.x * 128, m0 = blockIdx.y * 128;
    const int wm = (wid >> 2) * 64;
    const int wn = (wid & 3) * 32;

    float acc[4][4][4];
#pragma unroll
    for (int i = 0; i < 4; i++)
#pragma unroll
        for (int j = 0; j < 4; j++)
#pragma unroll
            for (int q = 0; q < 4; q++) acc[i][j][q] = 0.0f;

    GEMM_MAINLOOP(ah, al, wh, wl, m0, n0)

    const int lr = lane >> 2;
    const int lc = (lane & 3) * 2;
#pragma unroll
    for (int mi = 0; mi < 4; mi++) {
#pragma unroll
        for (int ni = 0; ni < 4; ni++) {
            int col = n0 + wn + ni * 8 + lc;
            float bx = 0.0f, by = 0.0f;
            if (BIAS) { bx = bias[col]; by = bias[col + 1]; }
            int row0 = m0 + wm + mi * 16 + lr;
            float v[4];
            v[0] = acc[mi][ni][0] + bx; v[1] = acc[mi][ni][1] + by;
            v[2] = acc[mi][ni][2] + bx; v[3] = acc[mi][ni][3] + by;
            size_t o0 = (size_t)row0 * DMODEL + col;
            size_t o1 = (size_t)(row0 + 8) * DMODEL + col;
            if (RES) {
                float2 r0 = *(const float2*)&res[o0];
                float2 r1 = *(const float2*)&res[o1];
                v[0] += r0.x; v[1] += r0.y; v[2] += r1.x; v[3] += r1.y;
            }
            *(float2*)&C[o0] = make_float2(v[0], v[1]);
            *(float2*)&C[o1] = make_float2(v[2], v[3]);
        }
    }
}

// ---------------- fused QKVR GEMM: N=2048 (4 types x 512) ----------------
__global__ __launch_bounds__(256, 1)
void qkvr_gemm(const __nv_bfloat16* __restrict__ ah, const __nv_bfloat16* __restrict__ al,
               const __nv_bfloat16* __restrict__ wh, const __nv_bfloat16* __restrict__ wl,
               const float* __restrict__ bq, const float* __restrict__ bk,
               const float* __restrict__ bv, const float* __restrict__ br,
               __nv_bfloat16* __restrict__ qh, __nv_bfloat16* __restrict__ ql,
               __nv_bfloat16* __restrict__ kh, __nv_bfloat16* __restrict__ kl,
               __nv_bfloat16* __restrict__ vhp, __nv_bfloat16* __restrict__ vlp,
               float* __restrict__ rr) {
    extern __shared__ char smem[];
    const uint32_t smb = smem_to_u32(smem);
    const int tid = threadIdx.x;
    const int wid = tid >> 5, lane = tid & 31;
    const int n0 = blockIdx.x * 128, m0 = blockIdx.y * 128;
    const int wm = (wid >> 2) * 64;
    const int wn = (wid & 3) * 32;

    float acc[4][4][4];
#pragma unroll
    for (int i = 0; i < 4; i++)
#pragma unroll
        for (int j = 0; j < 4; j++)
#pragma unroll
            for (int q = 0; q < 4; q++) acc[i][j][q] = 0.0f;

    GEMM_MAINLOOP(ah, al, wh, wl, m0, n0)

    const int type = blockIdx.x >> 2;
    const int ncol0 = (blockIdx.x & 3) * 128;
    const float* bias = (type == 0) ? bq : (type == 1) ? bk : (type == 2) ? bv : br;
    const float scale = (type == 0) ? 0.125f : 1.0f;
    __nv_bfloat16* Hi = (type == 0) ? qh : (type == 1) ? kh : vhp;
    __nv_bfloat16* Lo = (type == 0) ? ql : (type == 1) ? kl : vlp;

    const int lr = lane >> 2;
    const int lc = (lane & 3) * 2;
#pragma unroll
    for (int mi = 0; mi < 4; mi++) {
#pragma unroll
        for (int ni = 0; ni < 4; ni++) {
            int col = ncol0 + wn + ni * 8 + lc;
            float bx = bias[col], by = bias[col + 1];
            int row0 = m0 + wm + mi * 16 + lr;
            float v[4];
            v[0] = acc[mi][ni][0] + bx; v[1] = acc[mi][ni][1] + by;
            v[2] = acc[mi][ni][2] + bx; v[3] = acc[mi][ni][3] + by;
            size_t o0 = (size_t)row0 * DMODEL + col;
            size_t o1 = (size_t)(row0 + 8) * DMODEL + col;
            if (type == 3) {
                *(float2*)&rr[o0] = make_float2(v[0], v[1]);
                *(float2*)&rr[o1] = make_float2(v[2], v[3]);
            } else {
                __nv_bfloat16 hv[4], lv[4];
#pragma unroll
                for (int q = 0; q < 4; q++) {
                    float sv = v[q] * scale;
                    __nv_bfloat16 hh = __float2bfloat16(sv);
                    hv[q] = hh;
                    lv[q] = __float2bfloat16(sv - __bfloat162float(hh));
                }
                *(uint32_t*)&Hi[o0] = *(uint32_t*)&hv[0];
                *(uint32_t*)&Hi[o1] = *(uint32_t*)&hv[2];
                *(uint32_t*)&Lo[o0] = *(uint32_t*)&lv[0];
                *(uint32_t*)&Lo[o1] = *(uint32_t*)&lv[2];
            }
        }
    }
}

// ---------------- mma flash attention (bf16 3-split, fp32 softmax) ----------------
// R9-exact (measured 91.9us): 128 q-rows/CTA, 256 thr, 2-stage 32KB KV (64-kv blocks),
// V row-major + ldmatrix.trans, epilogue fuses *R + bf16 split.
#define AT_SMEM (65536 + 512)

__global__ __launch_bounds__(256, 1)
void attn_mma(const __nv_bfloat16* __restrict__ qh, const __nv_bfloat16* __restrict__ ql,
              const __nv_bfloat16* __restrict__ kh, const __nv_bfloat16* __restrict__ kl,
              const __nv_bfloat16* __restrict__ vh, const __nv_bfloat16* __restrict__ vl,
              const int* __restrict__ mask, const float* __restrict__ rmul,
              __nv_bfloat16* __restrict__ oh, __nv_bfloat16* __restrict__ ol) {
    extern __shared__ char smem[];
    const uint32_t smb = smem_to_u32(smem);
    int* msk = (int*)(smem + 65536);
    const int tid = threadIdx.x;
    const int wid = tid >> 5, lane = tid & 31;
    const int b = blockIdx.z, h = blockIdx.y, q0 = blockIdx.x * 128;
    const int wm = wid * 16;
    const int lr = lane >> 2;
    const int lc = (lane & 3) * 2;

    // ---- stage Q (hi @0, lo @16384) ----
    {
        int row = tid >> 1;
        int g0 = (tid & 1) * 4;
        size_t gofs = (size_t)(b * SEQ + q0 + row) * DMODEL + h * DHEAD;
        const char* gqh = (const char*)(qh + gofs);
        const char* gql = (const char*)(ql + gofs);
        uint32_t srow = smb + row * 128;
#pragma unroll
        for (int j = 0; j < 4; j++) {
            int g = g0 + j;
            uint32_t so = (uint32_t)((g ^ (row & 7)) << 4);
            cp_async16(srow + so, gqh + g * 16);
            cp_async16(srow + 16384 + so, gql + g * 16);
        }
    }
    asm volatile("cp.async.commit_group;");
    asm volatile("cp.async.wait_group 0;");
    __syncthreads();

    uint32_t Qh_[4][4], Ql_[4][4];
    {
        int row = wm + (lane & 15);
#pragma unroll
        for (int k16 = 0; k16 < 4; k16++) {
            int g = k16 * 2 + (lane >> 4);
            uint32_t so = (uint32_t)(row * 128 + ((g ^ (row & 7)) << 4));
            ldsm4(Qh_[k16][0], Qh_[k16][1], Qh_[k16][2], Qh_[k16][3], smb + so);
            ldsm4(Ql_[k16][0], Ql_[k16][1], Ql_[k16][2], Ql_[k16][3], smb + 16384 + so);
        }
    }
    __syncthreads();   // Q smem region reused for KV stages

    float Of[8][4];
#pragma unroll
    for (int i = 0; i < 8; i++)
#pragma unroll
        for (int q = 0; q < 4; q++) Of[i][q] = 0.0f;
    float m0r = -1e30f, m1r = -1e30f, l0 = 0.0f, l1 = 0.0f;

    auto stage_kv = [&](int jt, int s) {
        int kv0 = jt * 64;
        int r = tid >> 2;
        int g0 = tid & 3;
        size_t gofs = (size_t)(b * SEQ + kv0 + r) * DMODEL + h * DHEAD;
        const char* pkh = (const char*)(kh + gofs);
        const char* pkl = (const char*)(kl + gofs);
        const char* pvh = (const char*)(vh + gofs);
        const char* pvl = (const char*)(vl + gofs);
        uint32_t base = smb + s * 32768 + r * 128;
#pragma unroll
        for (int t = 0; t < 2; t++) {
            int g = g0 + t * 4;
            uint32_t so = (uint32_t)((g ^ (r & 7)) << 4);
            cp_async16(base + so, pkh + g * 16);
            cp_async16(base + 8192 + so, pkl + g * 16);
            cp_async16(base + 16384 + so, pvh + g * 16);
            cp_async16(base + 24576 + so, pvl + g * 16);
        }
        if (tid < 64) msk[s * 64 + tid] = mask[b * SEQ + kv0 + tid];
    };

    stage_kv(0, 0);
    asm volatile("cp.async.commit_group;");

    for (int jt = 0; jt < SEQ / 64; jt++) {
        if (jt + 1 < SEQ / 64) {
            stage_kv(jt + 1, (jt + 1) & 1);
            asm volatile("cp.async.commit_group;");
            asm volatile("cp.async.wait_group 1;");
        } else {
            asm volatile("cp.async.wait_group 0;");
        }
        __syncthreads();
        const int s = jt & 1;
        const uint32_t Kbase = smb + s * 32768;
        const uint32_t Vbase = Kbase + 16384;
        const int* mskp = msk + s * 64;

        float S[8][4];
#pragma unroll
        for (int i = 0; i < 8; i++)
#pragma unroll
            for (int q = 0; q < 4; q++) S[i][q] = 0.0f;
#pragma unroll
        for (int k16 = 0; k16 < 4; k16++) {
#pragma unroll
            for (int nj = 0; nj < 4; nj++) {
                int row = nj * 16 + ((lane >> 4) << 3) + (lane & 7);
                int g = k16 * 2 + ((lane >> 3) & 1);
                uint32_t so = (uint32_t)(row * 128 + ((g ^ (row & 7)) << 4));
                uint32_t bh0, bh1, bh2, bh3, bl0, bl1, bl2, bl3;
                ldsm4(bh0, bh1, bh2, bh3, Kbase + so);
                ldsm4(bl0, bl1, bl2, bl3, Kbase + 8192 + so);
                mma16816(S[2 * nj], Qh_[k16][0], Qh_[k16][1], Qh_[k16][2], Qh_[k16][3], bh0, bh1);
                mma16816(S[2 * nj], Qh_[k16][0], Qh_[k16][1], Qh_[k16][2], Qh_[k16][3], bl0, bl1);
                mma16816(S[2 * nj], Ql_[k16][0], Ql_[k16][1], Ql_[k16][2], Ql_[k16][3], bh0, bh1);
                mma16816(S[2 * nj + 1], Qh_[k16][0], Qh_[k16][1], Qh_[k16][2], Qh_[k16][3], bh2, bh3);
                mma16816(S[2 * nj + 1], Qh_[k16][0], Qh_[k16][1], Qh_[k16][2], Qh_[k16][3], bl2, bl3);
                mma16816(S[2 * nj + 1], Ql_[k16][0], Ql_[k16][1], Ql_[k16][2], Ql_[k16][3], bh2, bh3);
            }
        }
#pragma unroll
        for (int ni = 0; ni < 8; ni++) {
            int j0 = ni * 8 + lc;
            if (mskp[j0] == 0)     { S[ni][0] = -1e10f; S[ni][2] = -1e10f; }
            if (mskp[j0 + 1] == 0) { S[ni][1] = -1e10f; S[ni][3] = -1e10f; }
        }
        float rmax0 = -1e30f, rmax1 = -1e30f;
#pragma unroll
        for (int ni = 0; ni < 8; ni++) {
            rmax0 = fmaxf(rmax0, fmaxf(S[ni][0], S[ni][1]));
            rmax1 = fmaxf(rmax1, fmaxf(S[ni][2], S[ni][3]));
        }
        rmax0 = fmaxf(rmax0, __shfl_xor_sync(0xffffffffu, rmax0, 1));
        rmax0 = fmaxf(rmax0, __shfl_xor_sync(0xffffffffu, rmax0, 2));
        rmax1 = fmaxf(rmax1, __shfl_xor_sync(0xffffffffu, rmax1, 1));
        rmax1 = fmaxf(rmax1, __shfl_xor_sync(0xffffffffu, rmax1, 2));
        float mn0 = fmaxf(m0r, rmax0), mn1 = fmaxf(m1r, rmax1);
        float corr0 = __expf(m0r - mn0), corr1 = __expf(m1r - mn1);
        m0r = mn0; m1r = mn1;
        float rs0 = 0.0f, rs1 = 0.0f;
#pragma unroll
        for (int ni = 0; ni < 8; ni++) {
            S[ni][0] = __expf(S[ni][0] - mn0); rs0 += S[ni][0];
            S[ni][1] = __expf(S[ni][1] - mn0); rs0 += S[ni][1];
            S[ni][2] = __expf(S[ni][2] - mn1); rs1 += S[ni][2];
            S[ni][3] = __expf(S[ni][3] - mn1); rs1 += S[ni][3];
        }
        rs0 += __shfl_xor_sync(0xffffffffu, rs0, 1);
        rs0 += __shfl_xor_sync(0xffffffffu, rs0, 2);
        rs1 += __shfl_xor_sync(0xffffffffu, rs1, 1);
        rs1 += __shfl_xor_sync(0xffffffffu, rs1, 2);
        l0 = l0 * corr0 + rs0;
        l1 = l1 * corr1 + rs1;
#pragma unroll
        for (int ni = 0; ni < 8; ni++) {
            Of[ni][0] *= corr0; Of[ni][1] *= corr0;
            Of[ni][2] *= corr1; Of[ni][3] *= corr1;
        }
#pragma unroll
        for (int k16 = 0; k16 < 4; k16++) {
            float2 f0 = make_float2(S[2 * k16][0], S[2 * k16][1]);
            float2 f1 = make_float2(S[2 * k16][2], S[2 * k16][3]);
            float2 f2 = make_float2(S[2 * k16 + 1][0], S[2 * k16 + 1][1]);
            float2 f3 = make_float2(S[2 * k16 + 1][2], S[2 * k16 + 1][3]);
            __nv_bfloat162 h0 = __float22bfloat162_rn(f0);
            __nv_bfloat162 h1 = __float22bfloat162_rn(f1);
            __nv_bfloat162 h2 = __float22bfloat162_rn(f2);
            __nv_bfloat162 h3 = __float22bfloat162_rn(f3);
            __nv_bfloat162 e0 = __float22bfloat162_rn(make_float2(f0.x - __low2float(h0), f0.y - __high2float(h0)));
            __nv_bfloat162 e1 = __float22bfloat162_rn(make_float2(f1.x - __low2float(h1), f1.y - __high2float(h1)));
            __nv_bfloat162 e2 = __float22bfloat162_rn(make_float2(f2.x - __low2float(h2), f2.y - __high2float(h2)));
            __nv_bfloat162 e3 = __float22bfloat162_rn(make_float2(f3.x - __low2float(h3), f3.y - __high2float(h3)));
            uint32_t ah0 = *(uint32_t*)&h0, ah1 = *(uint32_t*)&h1, ah2 = *(uint32_t*)&h2, ah3 = *(uint32_t*)&h3;
            uint32_t al0 = *(uint32_t*)&e0, al1 = *(uint32_t*)&e1, al2 = *(uint32_t*)&e2, al3 = *(uint32_t*)&e3;
            int quad = lane >> 3, lr8 = lane & 7;
            int vrow = k16 * 16 + (quad & 1) * 8 + lr8;
#pragma unroll
            for (int nj = 0; nj < 4; nj++) {
                int g = nj * 2 + (quad >> 1);
                uint32_t so = (uint32_t)(vrow * 128 + ((g ^ (vrow & 7)) << 4));
                uint32_t vh0, vh1, vh2, vh3, vl0, vl1, vl2, vl3;
                ldsm4t(vh0, vh1, vh2, vh3, Vbase + so);
                ldsm4t(vl0, vl1, vl2, vl3, Vbase + 8192 + so);
                mma16816(Of[2 * nj], ah0, ah1, ah2, ah3, vh0, vh1);
                mma16816(Of[2 * nj], ah0, ah1, ah2, ah3, vl0, vl1);
                mma16816(Of[2 * nj], al0, al1, al2, al3, vh0, vh1);
                mma16816(Of[2 * nj + 1], ah0, ah1, ah2, ah3, vh2, vh3);
                mma16816(Of[2 * nj + 1], ah0, ah1, ah2, ah3, vl2, vl3);
                mma16816(Of[2 * nj + 1], al0, al1, al2, al3, vh2, vh3);
            }
        }
        __syncthreads();
    }

    // ---- epilogue: (Of/l) * R  -> bf16 hi/lo split ----
    float inv0 = 1.0f / l0, inv1 = 1.0f / l1;
    int r0 = b * SEQ + q0 + wm + lr;
    int r1 = r0 + 8;
#pragma unroll
    for (int ni = 0; ni < 8; ni++) {
        int col = h * DHEAD + ni * 8 + lc;
        size_t o0 = (size_t)r0 * DMODEL + col;
        size_t o1 = (size_t)r1 * DMODEL + col;
        float2 rv0 = *(const float2*)&rmul[o0];
        float2 rv1 = *(const float2*)&rmul[o1];
        float v0 = Of[ni][0] * inv0 * rv0.x;
        float v1 = Of[ni][1] * inv0 * rv0.y;
        float v2 = Of[ni][2] * inv1 * rv1.x;
        float v3 = Of[ni][3] * inv1 * rv1.y;
        __nv_bfloat16 hv[4], lv[4];
        split_store(v0, &hv[0], &lv[0]);
        split_store(v1, &hv[1], &lv[1]);
        split_store(v2, &hv[2], &lv[2]);
        split_store(v3, &hv[3], &lv[3]);
        *(uint32_t*)&oh[o0] = *(uint32_t*)&hv[0];
        *(uint32_t*)&oh[o1] = *(uint32_t*)&hv[2];
        *(uint32_t*)&ol[o0] = *(uint32_t*)&lv[0];
        *(uint32_t*)&ol[o1] = *(uint32_t*)&lv[2];
    }
}

// ---------------- LN2 + KAN + split fused ----------------
__device__ __forceinline__ float2 bspline01(float x) {
    const float h = 2.0f / 7.0f;
    const float i1 = 3.5f;
    const float i2 = 1.75f;
    const float i3 = 7.0f / 6.0f;
    float B0[5];
#pragma unroll
    for (int kk = 0; kk < 5; kk++) {
        float tk = -1.0f + kk * h;
        B0[kk] = (x >= tk && x < tk + h) ? 1.0f : 0.0f;
    }
    float B1[4];
#pragma unroll
    for (int kk = 0; kk < 4; kk++) {
        float tk = -1.0f + kk * h;
        B1[kk] = (x - tk) * i1 * B0[kk] + ((tk + 2.0f * h) - x) * i1 * B0[kk + 1];
    }
    float B2[3];
#pragma unroll
    for (int kk = 0; kk < 3; kk++) {
        float tk = -1.0f + kk * h;
        B2[kk] = (x - tk) * i2 * B1[kk] + ((tk + 3.0f * h) - x) * i2 * B1[kk + 1];
    }
    float2 r;
    {
        float tk = -1.0f;
        r.x = (x - tk) * i3 * B2[0] + ((tk + 4.0f * h) - x) * i3 * B2[1];
        tk = -1.0f + h;
        r.y = (x - tk) * i3 * B2[1] + ((tk + 4.0f * h) - x) * i3 * B2[2];
    }
    return r;
}

__global__ void ln2_kan_split(const float* __restrict__ x,
                              const float* __restrict__ w, const float* __restrict__ b,
                              const float* __restrict__ ic,
                              __nv_bfloat16* __restrict__ hi,
                              __nv_bfloat16* __restrict__ lo) {
    int row = blockIdx.x, t = threadIdx.x;
    float4 o = ln_row(x, w, b, row, t);
    int d0 = t * 4;
    float zz[4] = {o.x, o.y, o.z, o.w};
    __nv_bfloat16 hv[4], lv[4];
#pragma unroll
    for (int q = 0; q < 4; q++) {
        float xv = tanhf(zz[q]);
        float2 bs = bspline01(xv);
        int d = d0 + q;
        float val = bs.x * ic[d * 5 + 0] + bs.y * ic[d * 5 + 1];
        split_store(val, &hv[q], &lv[q]);
    }
    int i = row * (DMODEL / 4) + t;
    ((uint64_t*)hi)[i] = *(uint64_t*)hv;
    ((uint64_t*)lo)[i] = *(uint64_t*)lv;
}

// ---------------- host ----------------
extern "C" void kernel_launch(void* const* d_in, const int* in_sizes, int n_in,
                              void* d_out, int out_size) {
    const float* src    = (const float*)d_in[0];
    const float* ln1_w  = (const float*)d_in[1];
    const float* ln1_b  = (const float*)d_in[2];
    const float* ln2_w  = (const float*)d_in[3];
    const float* ln2_b  = (const float*)d_in[4];
    const float* ln3_w  = (const float*)d_in[5];
    const float* ln3_b  = (const float*)d_in[6];
    const float* Wq_w   = (const float*)d_in[7];
    const float* Wq_b   = (const float*)d_in[8];
    const float* Wk_w   = (const float*)d_in[9];
    const float* Wk_b   = (const float*)d_in[10];
    const float* Wv_w   = (const float*)d_in[11];
    const float* Wv_b   = (const float*)d_in[12];
    const float* Wr_w   = (const float*)d_in[13];
    const float* Wr_b   = (const float*)d_in[14];
    const float* Wo_w   = (const float*)d_in[15];
    const float* Wo_b   = (const float*)d_in[16];
    const float* inner_c= (const float*)d_in[17];
    const float* outer_c= (const float*)d_in[18];
    const int*   mask   = (const int*)d_in[19];
    float* out = (float*)d_out;

    float *r;
    __nv_bfloat16 *wh, *wl, *ah, *al, *qh, *ql, *kh, *kl, *vh, *vl;
    cudaGetSymbolAddress((void**)&r, g_r);
    cudaGetSymbolAddress((void**)&wh, g_wh);
    cudaGetSymbolAddress((void**)&wl, g_wl);
    cudaGetSymbolAddress((void**)&ah, g_ah);
    cudaGetSymbolAddress((void**)&al, g_al);
    cudaGetSymbolAddress((void**)&qh, g_qh);
    cudaGetSymbolAddress((void**)&ql, g_ql);
    cudaGetSymbolAddress((void**)&kh, g_kh);
    cudaGetSymbolAddress((void**)&kl, g_kl);
    cudaGetSymbolAddress((void**)&vh, g_vh);
    cudaGetSymbolAddress((void**)&vl, g_vl);

    cudaFuncSetAttribute(attn_mma, cudaFuncAttributeMaxDynamicSharedMemorySize, AT_SMEM);
    cudaFuncSetAttribute(qkvr_gemm, cudaFuncAttributeMaxDynamicSharedMemorySize, GEMM_SMEM);
    cudaFuncSetAttribute(mma_gemm<true, true>, cudaFuncAttributeMaxDynamicSharedMemorySize, GEMM_SMEM);
    cudaFuncSetAttribute(mma_gemm<false, true>, cudaFuncAttributeMaxDynamicSharedMemorySize, GEMM_SMEM);

    // weights -> fused bf16 hi/lo, one launch
    {
        int n4 = 24 * MAT / 4;
        weight_prep<<<(n4 + 255) / 256, 256>>>(Wq_w, Wk_w, Wv_w, Wr_w, Wo_w, outer_c, wh, wl);
    }

    cudaMemcpyAsync(out, src, (size_t)ROWS * DMODEL * sizeof(float),
                    cudaMemcpyDeviceToDevice, 0);

    dim3 ggrid(DMODEL / 128, ROWS / 128);
    dim3 qgrid(2048 / 128, ROWS / 128);

    // ln1 for layer 0
    ln_split_kernel<<<ROWS, 128>>>(out, ln1_w, ln1_b, ah, al);

    for (int l = 0; l < NLAYER; l++) {
        const __nv_bfloat16* whQ = wh + (size_t)(4 * l) * MAT;
        const __nv_bfloat16* wlQ = wl + (size_t)(4 * l) * MAT;
        const __nv_bfloat16* whO = wh + (size_t)(16 + l) * MAT;
        const __nv_bfloat16* wlO = wl + (size_t)(16 + l) * MAT;
        const __nv_bfloat16* whC = wh + (size_t)(20 + l) * MAT;
        const __nv_bfloat16* wlC = wl + (size_t)(20 + l) * MAT;
        // --- attention block ---
        qkvr_gemm<<<qgrid, 256, GEMM_SMEM>>>(ah, al, whQ, wlQ,
                                             Wq_b + l * DMODEL, Wk_b + l * DMODEL,
                                             Wv_b + l * DMODEL, Wr_b + l * DMODEL,
                                             qh, ql, kh, kl, vh, vl, r);
        attn_mma<<<dim3(SEQ / 128, NHEAD, BSZ), 256, AT_SMEM>>>(qh, ql, kh, kl, vh, vl,
                                                                mask, r, ah, al);
        mma_gemm<true, true><<<ggrid, 256, GEMM_SMEM>>>(ah, al, whO, wlO, Wo_b + l * DMODEL, out, out);
        // --- KAN block ---
        ln2_kan_split<<<ROWS, 128>>>(out, ln2_w + l * DMODEL, ln2_b + l * DMODEL,
                                     inner_c + l * DMODEL * 5, ah, al);
        mma_gemm<false, true><<<ggrid, 256, GEMM_SMEM>>>(ah, al, whC, wlC, nullptr, out, out);
        // --- LN3 (+ next layer LN1 + split) ---
        if (l < NLAYER - 1) {
            ln3_ln1_kernel<<<ROWS, 128>>>(out, ln3_w + l * DMODEL, ln3_b + l * DMODEL,
                                          ln1_w + (l + 1) * DMODEL, ln1_b + (l + 1) * DMODEL,
                                          out, ah, al);
        } else {
            ln_kernel<<<ROWS, 128>>>(out, ln3_w + l * DMODEL, ln3_b + l * DMODEL, out);
        }
    }
}

// round 15
// speedup vs baseline: 1.0059x; 1.0059x over previous
#include <cuda_runtime.h>
#include <cuda_bf16.h>
#include <math.h>
#include <stdint.h>

// Problem constants
#define BSZ 4
#define SEQ 1024
#define DMODEL 512
#define NHEAD 8
#define DHEAD 64
#define NLAYER 4
#define ROWS (BSZ * SEQ)          // 4096
#define MAT (DMODEL * DMODEL)     // 262144

// ---------------- scratch (device globals; no allocation) ----------------
__device__ float g_r[ROWS * DMODEL];
__device__ __nv_bfloat16 g_wh[24 * MAT];
__device__ __nv_bfloat16 g_wl[24 * MAT];
__device__ __nv_bfloat16 g_ah[ROWS * DMODEL];
__device__ __nv_bfloat16 g_al[ROWS * DMODEL];
__device__ __nv_bfloat16 g_qh[ROWS * DMODEL];
__device__ __nv_bfloat16 g_ql[ROWS * DMODEL];
__device__ __nv_bfloat16 g_kh[ROWS * DMODEL];
__device__ __nv_bfloat16 g_kl[ROWS * DMODEL];
__device__ __nv_bfloat16 g_vh[ROWS * DMODEL];
__device__ __nv_bfloat16 g_vl[ROWS * DMODEL];

// ---------------- PTX helpers (sm_80+ features only) ----------------
__device__ __forceinline__ uint32_t smem_to_u32(const void* p) {
    uint32_t a;
    asm("{ .reg .u64 t; cvta.to.shared.u64 t, %1; cvt.u32.u64 %0, t; }" : "=r"(a) : "l"(p));
    return a;
}
__device__ __forceinline__ void cp_async16(uint32_t dst, const void* src) {
    asm volatile("cp.async.cg.shared.global [%0], [%1], 16;" :: "r"(dst), "l"(src));
}
__device__ __forceinline__ void ldsm4(uint32_t& r0, uint32_t& r1, uint32_t& r2, uint32_t& r3,
                                      uint32_t a) {
    asm volatile("ldmatrix.sync.aligned.m8n8.x4.shared.b16 {%0,%1,%2,%3}, [%4];"
                 : "=r"(r0), "=r"(r1), "=r"(r2), "=r"(r3) : "r"(a));
}
__device__ __forceinline__ void ldsm4t(uint32_t& r0, uint32_t& r1, uint32_t& r2, uint32_t& r3,
                                       uint32_t a) {
    asm volatile("ldmatrix.sync.aligned.m8n8.x4.trans.shared.b16 {%0,%1,%2,%3}, [%4];"
                 : "=r"(r0), "=r"(r1), "=r"(r2), "=r"(r3) : "r"(a));
}
__device__ __forceinline__ void mma16816(float* c, uint32_t a0, uint32_t a1, uint32_t a2,
                                         uint32_t a3, uint32_t b0, uint32_t b1) {
    asm volatile(
        "mma.sync.aligned.m16n8k16.row.col.f32.bf16.bf16.f32 "
        "{%0,%1,%2,%3}, {%4,%5,%6,%7}, {%8,%9}, {%0,%1,%2,%3};"
        : "+f"(c[0]), "+f"(c[1]), "+f"(c[2]), "+f"(c[3])
        : "r"(a0), "r"(a1), "r"(a2), "r"(a3), "r"(b0), "r"(b1));
}

__device__ __forceinline__ void split_store(float v, __nv_bfloat16* hi, __nv_bfloat16* lo) {
    __nv_bfloat16 h = __float2bfloat16(v);
    *hi = h;
    *lo = __float2bfloat16(v - __bfloat162float(h));
}

// ---------------- warp-per-row LayerNorm family ----------------
// Each row (512 floats) is owned by ONE warp: 16 floats/thread, shuffle-only
// reductions, no smem, no __syncthreads. Block = 256 thr = 8 rows; grid = 512.
#define LN_GRID (ROWS / 8)
#define LN_BLK 256

__device__ __forceinline__ void warp_stats(const float4 v[4], float& mu, float& inv) {
    float s = 0.0f, sq = 0.0f;
#pragma unroll
    for (int j = 0; j < 4; j++) {
        s += v[j].x + v[j].y + v[j].z + v[j].w;
        sq += v[j].x * v[j].x + v[j].y * v[j].y + v[j].z * v[j].z + v[j].w * v[j].w;
    }
#pragma unroll
    for (int o = 16; o; o >>= 1) {
        s += __shfl_xor_sync(0xffffffffu, s, o);
        sq += __shfl_xor_sync(0xffffffffu, sq, o);
    }
    mu = s * (1.0f / DMODEL);
    float var = sq * (1.0f / DMODEL) - mu * mu;
    inv = rsqrtf(var + 1e-5f);
}

__device__ __forceinline__ void ln_apply(const float4 v[4], float mu, float inv,
                                         const float* __restrict__ w,
                                         const float* __restrict__ b,
                                         int lane, float4 o[4]) {
    const float4* wp = (const float4*)w;
    const float4* bp = (const float4*)b;
#pragma unroll
    for (int j = 0; j < 4; j++) {
        float4 wv = wp[lane + j * 32];
        float4 bv = bp[lane + j * 32];
        o[j].x = (v[j].x - mu) * inv * wv.x + bv.x;
        o[j].y = (v[j].y - mu) * inv * wv.y + bv.y;
        o[j].z = (v[j].z - mu) * inv * wv.z + bv.z;
        o[j].w = (v[j].w - mu) * inv * wv.w + bv.w;
    }
}

__global__ void ln_kernel(const float* __restrict__ x,
                          const float* __restrict__ w,
                          const float* __restrict__ b,
                          float* __restrict__ y) {
    int warp = threadIdx.x >> 5, lane = threadIdx.x & 31;
    int row = blockIdx.x * 8 + warp;
    const float4* p = (const float4*)(x + (size_t)row * DMODEL);
    float4 v[4];
#pragma unroll
    for (int j = 0; j < 4; j++) v[j] = p[lane + j * 32];
    float mu, inv;
    warp_stats(v, mu, inv);
    float4 o[4];
    ln_apply(v, mu, inv, w, b, lane, o);
    float4* yp = (float4*)(y + (size_t)row * DMODEL);
#pragma unroll
    for (int j = 0; j < 4; j++) yp[lane + j * 32] = o[j];
}

__global__ void ln_split_kernel(const float* __restrict__ x,
                                const float* __restrict__ w,
                                const float* __restrict__ b,
                                __nv_bfloat16* __restrict__ hi,
                                __nv_bfloat16* __restrict__ lo) {
    int warp = threadIdx.x >> 5, lane = threadIdx.x & 31;
    int row = blockIdx.x * 8 + warp;
    const float4* p = (const float4*)(x + (size_t)row * DMODEL);
    float4 v[4];
#pragma unroll
    for (int j = 0; j < 4; j++) v[j] = p[lane + j * 32];
    float mu, inv;
    warp_stats(v, mu, inv);
    float4 o[4];
    ln_apply(v, mu, inv, w, b, lane, o);
#pragma unroll
    for (int j = 0; j < 4; j++) {
        __nv_bfloat16 hv[4], lv[4];
        split_store(o[j].x, &hv[0], &lv[0]);
        split_store(o[j].y, &hv[1], &lv[1]);
        split_store(o[j].z, &hv[2], &lv[2]);
        split_store(o[j].w, &hv[3], &lv[3]);
        int i = row * (DMODEL / 4) + lane + j * 32;
        ((uint64_t*)hi)[i] = *(uint64_t*)hv;
        ((uint64_t*)lo)[i] = *(uint64_t*)lv;
    }
}

// LN3 then LN1(next layer), fused, warp-per-row
__global__ void ln3_ln1_kernel(const float* __restrict__ x,
                               const float* __restrict__ w3, const float* __restrict__ b3,
                               const float* __restrict__ w1, const float* __restrict__ b1,
                               float* __restrict__ y,
                               __nv_bfloat16* __restrict__ hi,
                               __nv_bfloat16* __restrict__ lo) {
    int warp = threadIdx.x >> 5, lane = threadIdx.x & 31;
    int row = blockIdx.x * 8 + warp;
    const float4* p = (const float4*)(x + (size_t)row * DMODEL);
    float4 v[4];
#pragma unroll
    for (int j = 0; j < 4; j++) v[j] = p[lane + j * 32];
    float mu, inv;
    warp_stats(v, mu, inv);
    float4 o3[4];
    ln_apply(v, mu, inv, w3, b3, lane, o3);
    float4* yp = (float4*)(y + (size_t)row * DMODEL);
#pragma unroll
    for (int j = 0; j < 4; j++) yp[lane + j * 32] = o3[j];
    // second LN on o3
    warp_stats(o3, mu, inv);
    float4 o1[4];
    ln_apply(o3, mu, inv, w1, b1, lane, o1);
#pragma unroll
    for (int j = 0; j < 4; j++) {
        __nv_bfloat16 hv[4], lv[4];
        split_store(o1[j].x, &hv[0], &lv[0]);
        split_store(o1[j].y, &hv[1], &lv[1]);
        split_store(o1[j].z, &hv[2], &lv[2]);
        split_store(o1[j].w, &hv[3], &lv[3]);
        int i = row * (DMODEL / 4) + lane + j * 32;
        ((uint64_t*)hi)[i] = *(uint64_t*)hv;
        ((uint64_t*)lo)[i] = *(uint64_t*)lv;
    }
}

// ---------------- weight prep ----------------
__global__ void weight_prep(const float* __restrict__ Wq, const float* __restrict__ Wk,
                            const float* __restrict__ Wv, const float* __restrict__ Wr,
                            const float* __restrict__ Wo, const float* __restrict__ Oc,
                            __nv_bfloat16* __restrict__ wh, __nv_bfloat16* __restrict__ wl) {
    int i = blockIdx.x * blockDim.x + threadIdx.x;
    const int per = MAT / 4;
    if (i >= 24 * per) return;
    int s = i / per;
    int off = i - s * per;
    const float* src;
    if (s < 16) {
        int l = s >> 2, t = s & 3;
        src = (t == 0 ? Wq : t == 1 ? Wk : t == 2 ? Wv : Wr) + (size_t)l * MAT;
    } else if (s < 20) {
        src = Wo + (size_t)(s - 16) * MAT;
    } else {
        src = Oc + (size_t)(s - 20) * MAT;
    }
    float4 v = ((const float4*)src)[off];
    __nv_bfloat16 hv[4], lv[4];
    split_store(v.x, &hv[0], &lv[0]);
    split_store(v.y, &hv[1], &lv[1]);
    split_store(v.z, &hv[2], &lv[2]);
    split_store(v.w, &hv[3], &lv[3]);
    ((uint64_t*)wh)[i] = *(uint64_t*)hv;
    ((uint64_t*)wl)[i] = *(uint64_t*)lv;
}

// ---------------- shared GEMM mainloop (tile-once 3-split, 2-stage) ----------
#define GEMM_SMEM 131072
#define NCHUNK 8

__device__ __forceinline__ void gemm_stage(uint32_t smb, int tid, int m0, int n0, int kc, int s,
                                           const __nv_bfloat16* ah, const __nv_bfloat16* al,
                                           const __nv_bfloat16* wh, const __nv_bfloat16* wl) {
    int row = tid >> 1;
    int g0 = (tid & 1) * 4;
    const char* pa0 = (const char*)(ah + (size_t)(m0 + row) * DMODEL + kc);
    const char* pa1 = (const char*)(al + (size_t)(m0 + row) * DMODEL + kc);
    const char* pb0 = (const char*)(wh + (size_t)(n0 + row) * DMODEL + kc);
    const char* pb1 = (const char*)(wl + (size_t)(n0 + row) * DMODEL + kc);
    uint32_t base = smb + s * 65536 + row * 128;
#pragma unroll
    for (int j = 0; j < 4; j++) {
        int g = g0 + j;
        uint32_t so = (uint32_t)((g ^ (row & 7)) << 4);
        cp_async16(base + so, pa0 + g * 16);
        cp_async16(base + 16384 + so, pa1 + g * 16);
        cp_async16(base + 32768 + so, pb0 + g * 16);
        cp_async16(base + 49152 + so, pb1 + g * 16);
    }
}

__device__ __forceinline__ void gemm_compute(uint32_t smb, int s, int wm, int wn, int lane,
                                             float acc[4][4][4]) {
    uint32_t A0 = smb + s * 65536;
    uint32_t A1 = A0 + 16384;
    uint32_t B0 = A0 + 32768;
    uint32_t B1 = A0 + 49152;
#pragma unroll
    for (int k16 = 0; k16 < 4; k16++) {
        uint32_t aH[4][4], aL[4][4];
#pragma unroll
        for (int mi = 0; mi < 4; mi++) {
            int row = wm + mi * 16 + (lane & 15);
            int g = k16 * 2 + (lane >> 4);
            uint32_t so = (uint32_t)(row * 128 + ((g ^ (row & 7)) << 4));
            ldsm4(aH[mi][0], aH[mi][1], aH[mi][2], aH[mi][3], A0 + so);
            ldsm4(aL[mi][0], aL[mi][1], aL[mi][2], aL[mi][3], A1 + so);
        }
        uint32_t bH[2][4], bL[2][4];
#pragma unroll
        for (int nj = 0; nj < 2; nj++) {
            int row = wn + nj * 16 + ((lane >> 4) << 3) + (lane & 7);
            int g = k16 * 2 + ((lane >> 3) & 1);
            uint32_t so = (uint32_t)(row * 128 + ((g ^ (row & 7)) << 4));
            ldsm4(bH[nj][0], bH[nj][1], bH[nj][2], bH[nj][3], B0 + so);
            ldsm4(bL[nj][0], bL[nj][1], bL[nj][2], bL[nj][3], B1 + so);
        }
#pragma unroll
        for (int mi = 0; mi < 4; mi++)
#pragma unroll
            for (int ni = 0; ni < 4; ni++) {
                uint32_t h0 = bH[ni >> 1][(ni & 1) * 2], h1 = bH[ni >> 1][(ni & 1) * 2 + 1];
                uint32_t l0 = bL[ni >> 1][(ni & 1) * 2], l1 = bL[ni >> 1][(ni & 1) * 2 + 1];
                mma16816(acc[mi][ni], aH[mi][0], aH[mi][1], aH[mi][2], aH[mi][3], h0, h1);
                mma16816(acc[mi][ni], aH[mi][0], aH[mi][1], aH[mi][2], aH[mi][3], l0, l1);
                mma16816(acc[mi][ni], aL[mi][0], aL[mi][1], aL[mi][2], aL[mi][3], h0, h1);
            }
    }
}

#define GEMM_MAINLOOP(AH, AL, WHp, WLp, M0, N0)                                      \
    gemm_stage(smb, tid, M0, N0, 0, 0, AH, AL, WHp, WLp);                            \
    asm volatile("cp.async.commit_group;");                                          \
    gemm_stage(smb, tid, M0, N0, 64, 1, AH, AL, WHp, WLp);                           \
    asm volatile("cp.async.commit_group;");                                          \
    for (int c = 0; c < NCHUNK; c++) {                                               \
        if (c < NCHUNK - 1) asm volatile("cp.async.wait_group 1;");                  \
        else                asm volatile("cp.async.wait_group 0;");                  \
        __syncthreads();                                                             \
        gemm_compute(smb, c & 1, wm, wn, lane, acc);                                 \
        __syncthreads();                                                             \
        if (c + 2 < NCHUNK) {                                                        \
            gemm_stage(smb, tid, M0, N0, (c + 2) * 64, c & 1, AH, AL, WHp, WLp);     \
            asm volatile("cp.async.commit_group;");                                  \
        }                                                                            \
    }

// ---------------- standard GEMM (fp32 out, +bias +res) ----------------
template <bool BIAS, bool RES>
__global__ __launch_bounds__(256, 1)
void mma_gemm(const __nv_bfloat16* __restrict__ ah, const __nv_bfloat16* __restrict__ al,
              const __nv_bfloat16* __restrict__ wh, const __nv_bfloat16* __restrict__ wl,
              const float* __restrict__ bias, const float* __restrict__ res,
              float* __restrict__ C) {
    extern __shared__ char smem[];
    const uint32_t smb = smem_to_u32(smem);
    const int tid = threadIdx.x;
    const int wid = tid >> 5, lane = tid & 31;
    const int n0 = blockIdx.x * 128, m0 = blockIdx.y * 128;
    const int wm = (wid >> 2) * 64;
    const int wn = (wid & 3) * 32;

    float acc[4][4][4];
#pragma unroll
    for (int i = 0; i < 4; i++)
#pragma unroll
        for (int j = 0; j < 4; j++)
#pragma unroll
            for (int q = 0; q < 4; q++) acc[i][j][q] = 0.0f;

    GEMM_MAINLOOP(ah, al, wh, wl, m0, n0)

    const int lr = lane >> 2;
    const int lc = (lane & 3) * 2;
#pragma unroll
    for (int mi = 0; mi < 4; mi++) {
#pragma unroll
        for (int ni = 0; ni < 4; ni++) {
            int col = n0 + wn + ni * 8 + lc;
            float bx = 0.0f, by = 0.0f;
            if (BIAS) { bx = bias[col]; by = bias[col + 1]; }
            int row0 = m0 + wm + mi * 16 + lr;
            float v[4];
            v[0] = acc[mi][ni][0] + bx; v[1] = acc[mi][ni][1] + by;
            v[2] = acc[mi][ni][2] + bx; v[3] = acc[mi][ni][3] + by;
            size_t o0 = (size_t)row0 * DMODEL + col;
            size_t o1 = (size_t)(row0 + 8) * DMODEL + col;
            if (RES) {
                float2 r0 = *(const float2*)&res[o0];
                float2 r1 = *(const float2*)&res[o1];
                v[0] += r0.x; v[1] += r0.y; v[2] += r1.x; v[3] += r1.y;
            }
            *(float2*)&C[o0] = make_float2(v[0], v[1]);
            *(float2*)&C[o1] = make_float2(v[2], v[3]);
        }
    }
}

// ---------------- fused QKVR GEMM: N=2048 (4 types x 512) ----------------
__global__ __launch_bounds__(256, 1)
void qkvr_gemm(const __nv_bfloat16* __restrict__ ah, const __nv_bfloat16* __restrict__ al,
               const __nv_bfloat16* __restrict__ wh, const __nv_bfloat16* __restrict__ wl,
               const float* __restrict__ bq, const float* __restrict__ bk,
               const float* __restrict__ bv, const float* __restrict__ br,
               __nv_bfloat16* __restrict__ qh, __nv_bfloat16* __restrict__ ql,
               __nv_bfloat16* __restrict__ kh, __nv_bfloat16* __restrict__ kl,
               __nv_bfloat16* __restrict__ vhp, __nv_bfloat16* __restrict__ vlp,
               float* __restrict__ rr) {
    extern __shared__ char smem[];
    const uint32_t smb = smem_to_u32(smem);
    const int tid = threadIdx.x;
    const int wid = tid >> 5, lane = tid & 31;
    const int n0 = blockIdx.x * 128, m0 = blockIdx.y * 128;
    const int wm = (wid >> 2) * 64;
    const int wn = (wid & 3) * 32;

    float acc[4][4][4];
#pragma unroll
    for (int i = 0; i < 4; i++)
#pragma unroll
        for (int j = 0; j < 4; j++)
#pragma unroll
            for (int q = 0; q < 4; q++) acc[i][j][q] = 0.0f;

    GEMM_MAINLOOP(ah, al, wh, wl, m0, n0)

    const int type = blockIdx.x >> 2;
    const int ncol0 = (blockIdx.x & 3) * 128;
    const float* bias = (type == 0) ? bq : (type == 1) ? bk : (type == 2) ? bv : br;
    const float scale = (type == 0) ? 0.125f : 1.0f;
    __nv_bfloat16* Hi = (type == 0) ? qh : (type == 1) ? kh : vhp;
    __nv_bfloat16* Lo = (type == 0) ? ql : (type == 1) ? kl : vlp;

    const int lr = lane >> 2;
    const int lc = (lane & 3) * 2;
#pragma unroll
    for (int mi = 0; mi < 4; mi++) {
#pragma unroll
        for (int ni = 0; ni < 4; ni++) {
            int col = ncol0 + wn + ni * 8 + lc;
            float bx = bias[col], by = bias[col + 1];
            int row0 = m0 + wm + mi * 16 + lr;
            float v[4];
            v[0] = acc[mi][ni][0] + bx; v[1] = acc[mi][ni][1] + by;
            v[2] = acc[mi][ni][2] + bx; v[3] = acc[mi][ni][3] + by;
            size_t o0 = (size_t)row0 * DMODEL + col;
            size_t o1 = (size_t)(row0 + 8) * DMODEL + col;
            if (type == 3) {
                *(float2*)&rr[o0] = make_float2(v[0], v[1]);
                *(float2*)&rr[o1] = make_float2(v[2], v[3]);
            } else {
                __nv_bfloat16 hv[4], lv[4];
#pragma unroll
                for (int q = 0; q < 4; q++) {
                    float sv = v[q] * scale;
                    __nv_bfloat16 hh = __float2bfloat16(sv);
                    hv[q] = hh;
                    lv[q] = __float2bfloat16(sv - __bfloat162float(hh));
                }
                *(uint32_t*)&Hi[o0] = *(uint32_t*)&hv[0];
                *(uint32_t*)&Hi[o1] = *(uint32_t*)&hv[2];
                *(uint32_t*)&Lo[o0] = *(uint32_t*)&lv[0];
                *(uint32_t*)&Lo[o1] = *(uint32_t*)&lv[2];
            }
        }
    }
}

// ---------------- mma flash attention (bf16 3-split, fp32 softmax) ----------------
// R9-exact: 128 q-rows/CTA, 256 thr, 2-stage 32KB KV (64-kv blocks),
// V row-major + ldmatrix.trans, epilogue fuses *R + bf16 split.
#define AT_SMEM (65536 + 512)

__global__ __launch_bounds__(256, 1)
void attn_mma(const __nv_bfloat16* __restrict__ qh, const __nv_bfloat16* __restrict__ ql,
              const __nv_bfloat16* __restrict__ kh, const __nv_bfloat16* __restrict__ kl,
              const __nv_bfloat16* __restrict__ vh, const __nv_bfloat16* __restrict__ vl,
              const int* __restrict__ mask, const float* __restrict__ rmul,
              __nv_bfloat16* __restrict__ oh, __nv_bfloat16* __restrict__ ol) {
    extern __shared__ char smem[];
    const uint32_t smb = smem_to_u32(smem);
    int* msk = (int*)(smem + 65536);
    const int tid = threadIdx.x;
    const int wid = tid >> 5, lane = tid & 31;
    const int b = blockIdx.z, h = blockIdx.y, q0 = blockIdx.x * 128;
    const int wm = wid * 16;
    const int lr = lane >> 2;
    const int lc = (lane & 3) * 2;

    {
        int row = tid >> 1;
        int g0 = (tid & 1) * 4;
        size_t gofs = (size_t)(b * SEQ + q0 + row) * DMODEL + h * DHEAD;
        const char* gqh = (const char*)(qh + gofs);
        const char* gql = (const char*)(ql + gofs);
        uint32_t srow = smb + row * 128;
#pragma unroll
        for (int j = 0; j < 4; j++) {
            int g = g0 + j;
            uint32_t so = (uint32_t)((g ^ (row & 7)) << 4);
            cp_async16(srow + so, gqh + g * 16);
            cp_async16(srow + 16384 + so, gql + g * 16);
        }
    }
    asm volatile("cp.async.commit_group;");
    asm volatile("cp.async.wait_group 0;");
    __syncthreads();

    uint32_t Qh_[4][4], Ql_[4][4];
    {
        int row = wm + (lane & 15);
#pragma unroll
        for (int k16 = 0; k16 < 4; k16++) {
            int g = k16 * 2 + (lane >> 4);
            uint32_t so = (uint32_t)(row * 128 + ((g ^ (row & 7)) << 4));
            ldsm4(Qh_[k16][0], Qh_[k16][1], Qh_[k16][2], Qh_[k16][3], smb + so);
            ldsm4(Ql_[k16][0], Ql_[k16][1], Ql_[k16][2], Ql_[k16][3], smb + 16384 + so);
        }
    }
    __syncthreads();

    float Of[8][4];
#pragma unroll
    for (int i = 0; i < 8; i++)
#pragma unroll
        for (int q = 0; q < 4; q++) Of[i][q] = 0.0f;
    float m0r = -1e30f, m1r = -1e30f, l0 = 0.0f, l1 = 0.0f;

    auto stage_kv = [&](int jt, int s) {
        int kv0 = jt * 64;
        int r = tid >> 2;
        int g0 = tid & 3;
        size_t gofs = (size_t)(b * SEQ + kv0 + r) * DMODEL + h * DHEAD;
        const char* pkh = (const char*)(kh + gofs);
        const char* pkl = (const char*)(kl + gofs);
        const char* pvh = (const char*)(vh + gofs);
        const char* pvl = (const char*)(vl + gofs);
        uint32_t base = smb + s * 32768 + r * 128;
#pragma unroll
        for (int t = 0; t < 2; t++) {
            int g = g0 + t * 4;
            uint32_t so = (uint32_t)((g ^ (r & 7)) << 4);
            cp_async16(base + so, pkh + g * 16);
            cp_async16(base + 8192 + so, pkl + g * 16);
            cp_async16(base + 16384 + so, pvh + g * 16);
            cp_async16(base + 24576 + so, pvl + g * 16);
        }
        if (tid < 64) msk[s * 64 + tid] = mask[b * SEQ + kv0 + tid];
    };

    stage_kv(0, 0);
    asm volatile("cp.async.commit_group;");

    for (int jt = 0; jt < SEQ / 64; jt++) {
        if (jt + 1 < SEQ / 64) {
            stage_kv(jt + 1, (jt + 1) & 1);
            asm volatile("cp.async.commit_group;");
            asm volatile("cp.async.wait_group 1;");
        } else {
            asm volatile("cp.async.wait_group 0;");
        }
        __syncthreads();
        const int s = jt & 1;
        const uint32_t Kbase = smb + s * 32768;
        const uint32_t Vbase = Kbase + 16384;
        const int* mskp = msk + s * 64;

        float S[8][4];
#pragma unroll
        for (int i = 0; i < 8; i++)
#pragma unroll
            for (int q = 0; q < 4; q++) S[i][q] = 0.0f;
#pragma unroll
        for (int k16 = 0; k16 < 4; k16++) {
#pragma unroll
            for (int nj = 0; nj < 4; nj++) {
                int row = nj * 16 + ((lane >> 4) << 3) + (lane & 7);
                int g = k16 * 2 + ((lane >> 3) & 1);
                uint32_t so = (uint32_t)(row * 128 + ((g ^ (row & 7)) << 4));
                uint32_t bh0, bh1, bh2, bh3, bl0, bl1, bl2, bl3;
                ldsm4(bh0, bh1, bh2, bh3, Kbase + so);
                ldsm4(bl0, bl1, bl2, bl3, Kbase + 8192 + so);
                mma16816(S[2 * nj], Qh_[k16][0], Qh_[k16][1], Qh_[k16][2], Qh_[k16][3], bh0, bh1);
                mma16816(S[2 * nj], Qh_[k16][0], Qh_[k16][1], Qh_[k16][2], Qh_[k16][3], bl0, bl1);
                mma16816(S[2 * nj], Ql_[k16][0], Ql_[k16][1], Ql_[k16][2], Ql_[k16][3], bh0, bh1);
                mma16816(S[2 * nj + 1], Qh_[k16][0], Qh_[k16][1], Qh_[k16][2], Qh_[k16][3], bh2, bh3);
                mma16816(S[2 * nj + 1], Qh_[k16][0], Qh_[k16][1], Qh_[k16][2], Qh_[k16][3], bl2, bl3);
                mma16816(S[2 * nj + 1], Ql_[k16][0], Ql_[k16][1], Ql_[k16][2], Ql_[k16][3], bh2, bh3);
            }
        }
#pragma unroll
        for (int ni = 0; ni < 8; ni++) {
            int j0 = ni * 8 + lc;
            if (mskp[j0] == 0)     { S[ni][0] = -1e10f; S[ni][2] = -1e10f; }
            if (mskp[j0 + 1] == 0) { S[ni][1] = -1e10f; S[ni][3] = -1e10f; }
        }
        float rmax0 = -1e30f, rmax1 = -1e30f;
#pragma unroll
        for (int ni = 0; ni < 8; ni++) {
            rmax0 = fmaxf(rmax0, fmaxf(S[ni][0], S[ni][1]));
            rmax1 = fmaxf(rmax1, fmaxf(S[ni][2], S[ni][3]));
        }
        rmax0 = fmaxf(rmax0, __shfl_xor_sync(0xffffffffu, rmax0, 1));
        rmax0 = fmaxf(rmax0, __shfl_xor_sync(0xffffffffu, rmax0, 2));
        rmax1 = fmaxf(rmax1, __shfl_xor_sync(0xffffffffu, rmax1, 1));
        rmax1 = fmaxf(rmax1, __shfl_xor_sync(0xffffffffu, rmax1, 2));
        float mn0 = fmaxf(m0r, rmax0), mn1 = fmaxf(m1r, rmax1);
        float corr0 = __expf(m0r - mn0), corr1 = __expf(m1r - mn1);
        m0r = mn0; m1r = mn1;
        float rs0 = 0.0f, rs1 = 0.0f;
#pragma unroll
        for (int ni = 0; ni < 8; ni++) {
            S[ni][0] = __expf(S[ni][0] - mn0); rs0 += S[ni][0];
            S[ni][1] = __expf(S[ni][1] - mn0); rs0 += S[ni][1];
            S[ni][2] = __expf(S[ni][2] - mn1); rs1 += S[ni][2];
            S[ni][3] = __expf(S[ni][3] - mn1); rs1 += S[ni][3];
        }
        rs0 += __shfl_xor_sync(0xffffffffu, rs0, 1);
        rs0 += __shfl_xor_sync(0xffffffffu, rs0, 2);
        rs1 += __shfl_xor_sync(0xffffffffu, rs1, 1);
        rs1 += __shfl_xor_sync(0xffffffffu, rs1, 2);
        l0 = l0 * corr0 + rs0;
        l1 = l1 * corr1 + rs1;
#pragma unroll
        for (int ni = 0; ni < 8; ni++) {
            Of[ni][0] *= corr0; Of[ni][1] *= corr0;
            Of[ni][2] *= corr1; Of[ni][3] *= corr1;
        }
#pragma unroll
        for (int k16 = 0; k16 < 4; k16++) {
            float2 f0 = make_float2(S[2 * k16][0], S[2 * k16][1]);
            float2 f1 = make_float2(S[2 * k16][2], S[2 * k16][3]);
            float2 f2 = make_float2(S[2 * k16 + 1][0], S[2 * k16 + 1][1]);
            float2 f3 = make_float2(S[2 * k16 + 1][2], S[2 * k16 + 1][3]);
            __nv_bfloat162 h0 = __float22bfloat162_rn(f0);
            __nv_bfloat162 h1 = __float22bfloat162_rn(f1);
            __nv_bfloat162 h2 = __float22bfloat162_rn(f2);
            __nv_bfloat162 h3 = __float22bfloat162_rn(f3);
            __nv_bfloat162 e0 = __float22bfloat162_rn(make_float2(f0.x - __low2float(h0), f0.y - __high2float(h0)));
            __nv_bfloat162 e1 = __float22bfloat162_rn(make_float2(f1.x - __low2float(h1), f1.y - __high2float(h1)));
            __nv_bfloat162 e2 = __float22bfloat162_rn(make_float2(f2.x - __low2float(h2), f2.y - __high2float(h2)));
            __nv_bfloat162 e3 = __float22bfloat162_rn(make_float2(f3.x - __low2float(h3), f3.y - __high2float(h3)));
            uint32_t ah0 = *(uint32_t*)&h0, ah1 = *(uint32_t*)&h1, ah2 = *(uint32_t*)&h2, ah3 = *(uint32_t*)&h3;
            uint32_t al0 = *(uint32_t*)&e0, al1 = *(uint32_t*)&e1, al2 = *(uint32_t*)&e2, al3 = *(uint32_t*)&e3;
            int quad = lane >> 3, lr8 = lane & 7;
            int vrow = k16 * 16 + (quad & 1) * 8 + lr8;
#pragma unroll
            for (int nj = 0; nj < 4; nj++) {
                int g = nj * 2 + (quad >> 1);
                uint32_t so = (uint32_t)(vrow * 128 + ((g ^ (vrow & 7)) << 4));
                uint32_t vh0, vh1, vh2, vh3, vl0, vl1, vl2, vl3;
                ldsm4t(vh0, vh1, vh2, vh3, Vbase + so);
                ldsm4t(vl0, vl1, vl2, vl3, Vbase + 8192 + so);
                mma16816(Of[2 * nj], ah0, ah1, ah2, ah3, vh0, vh1);
                mma16816(Of[2 * nj], ah0, ah1, ah2, ah3, vl0, vl1);
                mma16816(Of[2 * nj], al0, al1, al2, al3, vh0, vh1);
                mma16816(Of[2 * nj + 1], ah0, ah1, ah2, ah3, vh2, vh3);
                mma16816(Of[2 * nj + 1], ah0, ah1, ah2, ah3, vl2, vl3);
                mma16816(Of[2 * nj + 1], al0, al1, al2, al3, vh2, vh3);
            }
        }
        __syncthreads();
    }

    float inv0 = 1.0f / l0, inv1 = 1.0f / l1;
    int r0 = b * SEQ + q0 + wm + lr;
    int r1 = r0 + 8;
#pragma unroll
    for (int ni = 0; ni < 8; ni++) {
        int col = h * DHEAD + ni * 8 + lc;
        size_t o0 = (size_t)r0 * DMODEL + col;
        size_t o1 = (size_t)r1 * DMODEL + col;
        float2 rv0 = *(const float2*)&rmul[o0];
        float2 rv1 = *(const float2*)&rmul[o1];
        float v0 = Of[ni][0] * inv0 * rv0.x;
        float v1 = Of[ni][1] * inv0 * rv0.y;
        float v2 = Of[ni][2] * inv1 * rv1.x;
        float v3 = Of[ni][3] * inv1 * rv1.y;
        __nv_bfloat16 hv[4], lv[4];
        split_store(v0, &hv[0], &lv[0]);
        split_store(v1, &hv[1], &lv[1]);
        split_store(v2, &hv[2], &lv[2]);
        split_store(v3, &hv[3], &lv[3]);
        *(uint32_t*)&oh[o0] = *(uint32_t*)&hv[0];
        *(uint32_t*)&oh[o1] = *(uint32_t*)&hv[2];
        *(uint32_t*)&ol[o0] = *(uint32_t*)&lv[0];
        *(uint32_t*)&ol[o1] = *(uint32_t*)&lv[2];
    }
}

// ---------------- LN2 + KAN + split fused (warp-per-row) ----------------
__device__ __forceinline__ float2 bspline01(float x) {
    const float h = 2.0f / 7.0f;
    const float i1 = 3.5f;
    const float i2 = 1.75f;
    const float i3 = 7.0f / 6.0f;
    float B0[5];
#pragma unroll
    for (int kk = 0; kk < 5; kk++) {
        float tk = -1.0f + kk * h;
        B0[kk] = (x >= tk && x < tk + h) ? 1.0f : 0.0f;
    }
    float B1[4];
#pragma unroll
    for (int kk = 0; kk < 4; kk++) {
        float tk = -1.0f + kk * h;
        B1[kk] = (x - tk) * i1 * B0[kk] + ((tk + 2.0f * h) - x) * i1 * B0[kk + 1];
    }
    float B2[3];
#pragma unroll
    for (int kk = 0; kk < 3; kk++) {
        float tk = -1.0f + kk * h;
        B2[kk] = (x - tk) * i2 * B1[kk] + ((tk + 3.0f * h) - x) * i2 * B1[kk + 1];
    }
    float2 r;
    {
        float tk = -1.0f;
        r.x = (x - tk) * i3 * B2[0] + ((tk + 4.0f * h) - x) * i3 * B2[1];
        tk = -1.0f + h;
        r.y = (x - tk) * i3 * B2[1] + ((tk + 4.0f * h) - x) * i3 * B2[2];
    }
    return r;
}

__global__ void ln2_kan_split(const float* __restrict__ x,
                              const float* __restrict__ w, const float* __restrict__ b,
                              const float* __restrict__ ic,
                              __nv_bfloat16* __restrict__ hi,
                              __nv_bfloat16* __restrict__ lo) {
    int warp = threadIdx.x >> 5, lane = threadIdx.x & 31;
    int row = blockIdx.x * 8 + warp;
    const float4* p = (const float4*)(x + (size_t)row * DMODEL);
    float4 v[4];
#pragma unroll
    for (int j = 0; j < 4; j++) v[j] = p[lane + j * 32];
    float mu, inv;
    warp_stats(v, mu, inv);
    float4 o[4];
    ln_apply(v, mu, inv, w, b, lane, o);
#pragma unroll
    for (int j = 0; j < 4; j++) {
        int d0 = (lane + j * 32) * 4;
        float zz[4] = {o[j].x, o[j].y, o[j].z, o[j].w};
        __nv_bfloat16 hv[4], lv[4];
#pragma unroll
        for (int q = 0; q < 4; q++) {
            float xv = tanhf(zz[q]);
            float2 bs = bspline01(xv);
            int d = d0 + q;
            float val = bs.x * ic[d * 5 + 0] + bs.y * ic[d * 5 + 1];
            split_store(val, &hv[q], &lv[q]);
        }
        int i = row * (DMODEL / 4) + lane + j * 32;
        ((uint64_t*)hi)[i] = *(uint64_t*)hv;
        ((uint64_t*)lo)[i] = *(uint64_t*)lv;
    }
}

// ---------------- host ----------------
extern "C" void kernel_launch(void* const* d_in, const int* in_sizes, int n_in,
                              void* d_out, int out_size) {
    const float* src    = (const float*)d_in[0];
    const float* ln1_w  = (const float*)d_in[1];
    const float* ln1_b  = (const float*)d_in[2];
    const float* ln2_w  = (const float*)d_in[3];
    const float* ln2_b  = (const float*)d_in[4];
    const float* ln3_w  = (const float*)d_in[5];
    const float* ln3_b  = (const float*)d_in[6];
    const float* Wq_w   = (const float*)d_in[7];
    const float* Wq_b   = (const float*)d_in[8];
    const float* Wk_w   = (const float*)d_in[9];
    const float* Wk_b   = (const float*)d_in[10];
    const float* Wv_w   = (const float*)d_in[11];
    const float* Wv_b   = (const float*)d_in[12];
    const float* Wr_w   = (const float*)d_in[13];
    const float* Wr_b   = (const float*)d_in[14];
    const float* Wo_w   = (const float*)d_in[15];
    const float* Wo_b   = (const float*)d_in[16];
    const float* inner_c= (const float*)d_in[17];
    const float* outer_c= (const float*)d_in[18];
    const int*   mask   = (const int*)d_in[19];
    float* out = (float*)d_out;

    float *r;
    __nv_bfloat16 *wh, *wl, *ah, *al, *qh, *ql, *kh, *kl, *vh, *vl;
    cudaGetSymbolAddress((void**)&r, g_r);
    cudaGetSymbolAddress((void**)&wh, g_wh);
    cudaGetSymbolAddress((void**)&wl, g_wl);
    cudaGetSymbolAddress((void**)&ah, g_ah);
    cudaGetSymbolAddress((void**)&al, g_al);
    cudaGetSymbolAddress((void**)&qh, g_qh);
    cudaGetSymbolAddress((void**)&ql, g_ql);
    cudaGetSymbolAddress((void**)&kh, g_kh);
    cudaGetSymbolAddress((void**)&kl, g_kl);
    cudaGetSymbolAddress((void**)&vh, g_vh);
    cudaGetSymbolAddress((void**)&vl, g_vl);

    cudaFuncSetAttribute(attn_mma, cudaFuncAttributeMaxDynamicSharedMemorySize, AT_SMEM);
    cudaFuncSetAttribute(qkvr_gemm, cudaFuncAttributeMaxDynamicSharedMemorySize, GEMM_SMEM);
    cudaFuncSetAttribute(mma_gemm<true, true>, cudaFuncAttributeMaxDynamicSharedMemorySize, GEMM_SMEM);
    cudaFuncSetAttribute(mma_gemm<false, true>, cudaFuncAttributeMaxDynamicSharedMemorySize, GEMM_SMEM);

    // weights -> fused bf16 hi/lo, one launch
    {
        int n4 = 24 * MAT / 4;
        weight_prep<<<(n4 + 255) / 256, 256>>>(Wq_w, Wk_w, Wv_w, Wr_w, Wo_w, outer_c, wh, wl);
    }

    cudaMemcpyAsync(out, src, (size_t)ROWS * DMODEL * sizeof(float),
                    cudaMemcpyDeviceToDevice, 0);

    dim3 ggrid(DMODEL / 128, ROWS / 128);
    dim3 qgrid(2048 / 128, ROWS / 128);

    // ln1 for layer 0
    ln_split_kernel<<<LN_GRID, LN_BLK>>>(out, ln1_w, ln1_b, ah, al);

    for (int l = 0; l < NLAYER; l++) {
        const __nv_bfloat16* whQ = wh + (size_t)(4 * l) * MAT;
        const __nv_bfloat16* wlQ = wl + (size_t)(4 * l) * MAT;
        const __nv_bfloat16* whO = wh + (size_t)(16 + l) * MAT;
        const __nv_bfloat16* wlO = wl + (size_t)(16 + l) * MAT;
        const __nv_bfloat16* whC = wh + (size_t)(20 + l) * MAT;
        const __nv_bfloat16* wlC = wl + (size_t)(20 + l) * MAT;
        // --- attention block ---
        qkvr_gemm<<<qgrid, 256, GEMM_SMEM>>>(ah, al, whQ, wlQ,
                                             Wq_b + l * DMODEL, Wk_b + l * DMODEL,
                                             Wv_b + l * DMODEL, Wr_b + l * DMODEL,
                                             qh, ql, kh, kl, vh, vl, r);
        attn_mma<<<dim3(SEQ / 128, NHEAD, BSZ), 256, AT_SMEM>>>(qh, ql, kh, kl, vh, vl,
                                                                mask, r, ah, al);
        mma_gemm<true, true><<<ggrid, 256, GEMM_SMEM>>>(ah, al, whO, wlO, Wo_b + l * DMODEL, out, out);
        // --- KAN block ---
        ln2_kan_split<<<LN_GRID, LN_BLK>>>(out, ln2_w + l * DMODEL, ln2_b + l * DMODEL,
                                           inner_c + l * DMODEL * 5, ah, al);
        mma_gemm<false, true><<<ggrid, 256, GEMM_SMEM>>>(ah, al, whC, wlC, nullptr, out, out);
        // --- LN3 (+ next layer LN1 + split) ---
        if (l < NLAYER - 1) {
            ln3_ln1_kernel<<<LN_GRID, LN_BLK>>>(out, ln3_w + l * DMODEL, ln3_b + l * DMODEL,
                                                ln1_w + (l + 1) * DMODEL, ln1_b + (l + 1) * DMODEL,
                                                out, ah, al);
        } else {
            ln_kernel<<<LN_GRID, LN_BLK>>>(out, ln3_w + l * DMODEL, ln3_b + l * DMODEL, out);
        }
    }
}